// round 6
// baseline (speedup 1.0000x reference)
#include <cuda_runtime.h>

#define EPS      1e-4f
#define FRAMES   4000
#define THREADS  512
#define CPT      8                 // elements per thread: 512*8 = 4096 >= 4000
#define NWARPS   (THREADS / 32)    // 16

__global__ __launch_bounds__(THREADS)
void cumnorm_kernel(const float* __restrict__ x, float* __restrict__ out)
{
    __shared__ float2 wsum[NWARPS];   // per-warp inclusive (sum, sumsq)

    const int tid  = threadIdx.x;
    const int lane = tid & 31;
    const int warp = tid >> 5;

    const size_t rowoff = (size_t)blockIdx.x * FRAMES;
    const float* __restrict__ xin  = x   + rowoff;
    float*       __restrict__ xout = out + rowoff;

    const int  e0     = CPT * tid;           // this thread's first element
    const bool active = (e0 < FRAMES);       // whole 8-elt chunk in/out (4000 % 8 == 0)

    // ---- load 8 contiguous elements (two float4, streaming) ----
    float4 a, b;
    if (active) {
        a = __ldcs(reinterpret_cast<const float4*>(xin + e0));
        b = __ldcs(reinterpret_cast<const float4*>(xin + e0 + 4));
    } else {
        a = make_float4(0.f, 0.f, 0.f, 0.f);
        b = a;
    }

    // ---- thread-local totals (sum, sumsq) over the 8 elements ----
    float r[CPT] = {a.x, a.y, a.z, a.w, b.x, b.y, b.z, b.w};
    float ts = 0.f, tq = 0.f;
    #pragma unroll
    for (int j = 0; j < CPT; ++j) {
        ts += r[j];
        tq  = fmaf(r[j], r[j], tq);
    }

    // ---- inclusive warp scan of (ts, tq) ----
    float is = ts, iq = tq;
    #pragma unroll
    for (int d = 1; d < 32; d <<= 1) {
        float as = __shfl_up_sync(0xffffffffu, is, d);
        float aq = __shfl_up_sync(0xffffffffu, iq, d);
        if (lane >= d) { is += as; iq += aq; }
    }

    // ---- cross-warp scan (16 entries, by warp 0) ----
    if (lane == 31) wsum[warp] = make_float2(is, iq);
    __syncthreads();

    if (warp == 0) {
        float ws = (lane < NWARPS) ? wsum[lane].x : 0.f;
        float wq = (lane < NWARPS) ? wsum[lane].y : 0.f;
        #pragma unroll
        for (int d = 1; d < NWARPS; d <<= 1) {
            float as = __shfl_up_sync(0xffffffffu, ws, d);
            float aq = __shfl_up_sync(0xffffffffu, wq, d);
            if (lane >= d) { ws += as; wq += aq; }
        }
        if (lane < NWARPS) wsum[lane] = make_float2(ws, wq);
    }
    __syncthreads();

    if (!active) return;

    // exclusive prefix over all elements preceding this thread's chunk
    const float2 wp = (warp > 0) ? wsum[warp - 1] : make_float2(0.f, 0.f);
    float ps = wp.x + (is - ts);
    float pq = wp.y + (iq - tq);

    // ---- normalize: out = (c*x - s) * rsqrt(c*q - s^2 + eps*c^2) ----
    float c = (float)e0;
    #pragma unroll
    for (int j = 0; j < CPT; ++j) {
        const float xv = r[j];
        ps += xv;
        pq  = fmaf(xv, xv, pq);
        c  += 1.f;
        const float ecc = (EPS * c) * c;
        const float den = fmaf(c, pq, fmaf(-ps, ps, ecc));  // c*q - s^2 + eps*c^2
        const float num = fmaf(c, xv, -ps);                 // c*x - s
        r[j] = num * rsqrtf(den);
    }

    __stcs(reinterpret_cast<float4*>(xout + e0),
           make_float4(r[0], r[1], r[2], r[3]));
    __stcs(reinterpret_cast<float4*>(xout + e0 + 4),
           make_float4(r[4], r[5], r[6], r[7]));
}

extern "C" void kernel_launch(void* const* d_in, const int* in_sizes, int n_in,
                              void* d_out, int out_size)
{
    const float* x = (const float*)d_in[0];
    float* outp    = (float*)d_out;
    const int rows = in_sizes[0] / FRAMES;   // 32 * 512 = 16384
    cumnorm_kernel<<<rows, THREADS>>>(x, outp);
}

// round 7
// speedup vs baseline: 1.5725x; 1.5725x over previous
#include <cuda_runtime.h>

#define EPS      1e-4f
#define FRAMES   4000
#define THREADS  256
#define CPT      16                // 250 active threads * 16 = 4000
#define NWARPS   (THREADS / 32)    // 8

__global__ __launch_bounds__(THREADS)
void cumnorm_kernel(const float* __restrict__ x, float* __restrict__ out)
{
    __shared__ float2 wsum[NWARPS];   // per-warp inclusive (sum, sumsq)

    const int tid  = threadIdx.x;
    const int lane = tid & 31;
    const int warp = tid >> 5;

    const size_t rowoff = (size_t)blockIdx.x * FRAMES;
    const float* __restrict__ xin  = x   + rowoff;
    float*       __restrict__ xout = out + rowoff;

    const int  e0     = CPT * tid;          // first element of this thread's segment
    const bool active = (e0 < FRAMES);      // whole 16-elt segment in/out (4000 % 16 == 0)

    // ---- load 16 contiguous elements (4x float4, issued back-to-back) ----
    float4 v0, v1, v2, v3;
    if (active) {
        const float4* p = reinterpret_cast<const float4*>(xin + e0);
        v0 = p[0]; v1 = p[1]; v2 = p[2]; v3 = p[3];
    } else {
        v0 = make_float4(0.f, 0.f, 0.f, 0.f);
        v1 = v0; v2 = v0; v3 = v0;
    }

    float r[CPT] = {v0.x, v0.y, v0.z, v0.w,
                    v1.x, v1.y, v1.z, v1.w,
                    v2.x, v2.y, v2.z, v2.w,
                    v3.x, v3.y, v3.z, v3.w};

    // ---- thread-local totals (sum, sumsq) ----
    float ts = 0.f, tq = 0.f;
    #pragma unroll
    for (int j = 0; j < CPT; ++j) {
        ts += r[j];
        tq  = fmaf(r[j], r[j], tq);
    }

    // ---- inclusive warp scan of (ts, tq) ----
    float is = ts, iq = tq;
    #pragma unroll
    for (int d = 1; d < 32; d <<= 1) {
        float as = __shfl_up_sync(0xffffffffu, is, d);
        float aq = __shfl_up_sync(0xffffffffu, iq, d);
        if (lane >= d) { is += as; iq += aq; }
    }

    // ---- cross-warp scan (8 entries) ----
    if (lane == 31) wsum[warp] = make_float2(is, iq);
    __syncthreads();

    if (warp == 0) {
        float ws = (lane < NWARPS) ? wsum[lane].x : 0.f;
        float wq = (lane < NWARPS) ? wsum[lane].y : 0.f;
        #pragma unroll
        for (int d = 1; d < NWARPS; d <<= 1) {
            float as = __shfl_up_sync(0xffffffffu, ws, d);
            float aq = __shfl_up_sync(0xffffffffu, wq, d);
            if (lane >= d) { ws += as; wq += aq; }
        }
        if (lane < NWARPS) wsum[lane] = make_float2(ws, wq);
    }
    __syncthreads();

    if (!active) return;

    // exclusive prefix over all elements preceding this thread's segment
    const float2 wp = (warp > 0) ? wsum[warp - 1] : make_float2(0.f, 0.f);
    float ps = wp.x + (is - ts);
    float pq = wp.y + (iq - tq);

    // ---- normalize: out = (c*x - s) * rsqrt(c*q - s^2 + eps*c^2) ----
    float c = (float)e0;
    #pragma unroll
    for (int j = 0; j < CPT; ++j) {
        const float xv = r[j];
        ps += xv;
        pq  = fmaf(xv, xv, pq);
        c  += 1.f;
        const float ecc = (EPS * c) * c;
        const float den = fmaf(c, pq, fmaf(-ps, ps, ecc));  // c*q - s^2 + eps*c^2
        const float num = fmaf(c, xv, -ps);                 // c*x - s
        r[j] = num * rsqrtf(den);
    }

    float4* po = reinterpret_cast<float4*>(xout + e0);
    po[0] = make_float4(r[0],  r[1],  r[2],  r[3]);
    po[1] = make_float4(r[4],  r[5],  r[6],  r[7]);
    po[2] = make_float4(r[8],  r[9],  r[10], r[11]);
    po[3] = make_float4(r[12], r[13], r[14], r[15]);
}

extern "C" void kernel_launch(void* const* d_in, const int* in_sizes, int n_in,
                              void* d_out, int out_size)
{
    const float* x = (const float*)d_in[0];
    float* outp    = (float*)d_out;
    const int rows = in_sizes[0] / FRAMES;   // 32 * 512 = 16384
    cumnorm_kernel<<<rows, THREADS>>>(x, outp);
}

// round 8
// speedup vs baseline: 1.8331x; 1.1657x over previous
#include <cuda_runtime.h>

#define EPS      1e-4f
#define FRAMES   4000
#define THREADS  256
#define TILE     (THREADS * 4)        // 1024 elements per tile
#define NTILES   4                    // 4 * 1024 = 4096 >= 4000
#define NWARPS   (THREADS / 32)       // 8

__global__ __launch_bounds__(THREADS)
void cumnorm_kernel(const float* __restrict__ x, float* __restrict__ out)
{
    __shared__ float2 wsum[NTILES * NWARPS];   // [tile][warp] inclusive (sum, sumsq)

    const int tid  = threadIdx.x;
    const int lane = tid & 31;
    const int warp = tid >> 5;

    const size_t rowoff = (size_t)blockIdx.x * FRAMES;
    const float* __restrict__ xin  = x   + rowoff;
    float*       __restrict__ xout = out + rowoff;

    // ---- issue ALL loads up front (coalesced float4, MLP=4 per thread) ----
    // tiles 0..2 are fully in range (max elem 3071 < 4000); only tile 3 needs a guard
    float4 v[NTILES];
    #pragma unroll
    for (int k = 0; k < NTILES; ++k) {
        const int e = k * TILE + 4 * tid;
        if (k < NTILES - 1 || e < FRAMES)
            v[k] = *reinterpret_cast<const float4*>(xin + e);
        else
            v[k] = make_float4(0.f, 0.f, 0.f, 0.f);
    }

    // ---- per-tile thread totals ----
    float ts[NTILES], tq[NTILES];
    #pragma unroll
    for (int k = 0; k < NTILES; ++k) {
        const float4 vk = v[k];
        ts[k] = (vk.x + vk.y) + (vk.z + vk.w);
        float q = vk.x * vk.x;
        q = fmaf(vk.y, vk.y, q);
        q = fmaf(vk.z, vk.z, q);
        tq[k] = fmaf(vk.w, vk.w, q);
    }

    // ---- 4 warp scans interleaved (8 independent shuffle chains) ----
    float is[NTILES], iq[NTILES];
    #pragma unroll
    for (int k = 0; k < NTILES; ++k) { is[k] = ts[k]; iq[k] = tq[k]; }
    #pragma unroll
    for (int d = 1; d < 32; d <<= 1) {
        #pragma unroll
        for (int k = 0; k < NTILES; ++k) {
            float as = __shfl_up_sync(0xffffffffu, is[k], d);
            float aq = __shfl_up_sync(0xffffffffu, iq[k], d);
            if (lane >= d) { is[k] += as; iq[k] += aq; }
        }
    }

    if (lane == 31) {
        #pragma unroll
        for (int k = 0; k < NTILES; ++k)
            wsum[k * NWARPS + warp] = make_float2(is[k], iq[k]);
    }
    __syncthreads();

    // ---- single segmented cross-warp scan: 32 entries = 4 segments of 8 ----
    if (warp == 0) {
        float2 w = wsum[lane];
        float ws = w.x, wq = w.y;
        #pragma unroll
        for (int d = 1; d < NWARPS; d <<= 1) {
            float as = __shfl_up_sync(0xffffffffu, ws, d);
            float aq = __shfl_up_sync(0xffffffffu, wq, d);
            if ((lane & (NWARPS - 1)) >= d) { ws += as; wq += aq; }
        }
        wsum[lane] = make_float2(ws, wq);
    }
    __syncthreads();

    // ---- inter-tile carry from the 4 tile totals (broadcast reads) ----
    float2 tot[NTILES];
    #pragma unroll
    for (int k = 0; k < NTILES; ++k) tot[k] = wsum[k * NWARPS + (NWARPS - 1)];

    float cs = 0.f, cq = 0.f;
    #pragma unroll
    for (int k = 0; k < NTILES; ++k) {
        // exclusive prefix before this thread's 4 elements in tile k
        float2 wp = (warp > 0) ? wsum[k * NWARPS + warp - 1] : make_float2(0.f, 0.f);
        float ps = cs + wp.x + (is[k] - ts[k]);
        float pq = cq + wp.y + (iq[k] - tq[k]);
        cs += tot[k].x;
        cq += tot[k].y;

        const int e = k * TILE + 4 * tid;
        if (k < NTILES - 1 || e < FRAMES) {
            float r[4] = {v[k].x, v[k].y, v[k].z, v[k].w};
            float c = (float)e;
            #pragma unroll
            for (int j = 0; j < 4; ++j) {
                const float xv = r[j];
                ps += xv;
                pq  = fmaf(xv, xv, pq);
                c  += 1.f;
                const float ecc = (EPS * c) * c;
                const float den = fmaf(c, pq, fmaf(-ps, ps, ecc)); // c*q - s^2 + eps*c^2
                const float num = fmaf(c, xv, -ps);                // c*x - s
                r[j] = num * rsqrtf(den);
            }
            *reinterpret_cast<float4*>(xout + e) =
                make_float4(r[0], r[1], r[2], r[3]);
        }
    }
}

extern "C" void kernel_launch(void* const* d_in, const int* in_sizes, int n_in,
                              void* d_out, int out_size)
{
    const float* x = (const float*)d_in[0];
    float* outp    = (float*)d_out;
    const int rows = in_sizes[0] / FRAMES;   // 32 * 512 = 16384
    cumnorm_kernel<<<rows, THREADS>>>(x, outp);
}